// round 6
// baseline (speedup 1.0000x reference)
#include <cuda_runtime.h>
#include <cfloat>
#include <math.h>

#define B_  1024
#define N_  50000
#define D_  256
#define MA_ 200
#define K_  8

// ---------- device scratch ----------
__device__ float g_qh[B_ * D_];
__device__ float g_mh[(size_t)N_ * D_];
__device__ float g_qsq[B_];
__device__ float g_msq[N_];
__device__ float g_arg[(size_t)B_ * N_];   // ~195 MB

// ---------- packed f32x2 helpers ----------
__device__ __forceinline__ unsigned long long pk2(float x, float y) {
    unsigned long long u;
    asm("mov.b64 %0, {%1,%2};" : "=l"(u) : "f"(x), "f"(y));
    return u;
}
__device__ __forceinline__ float2 up2(unsigned long long u) {
    float2 v;
    asm("mov.b64 {%0,%1}, %2;" : "=f"(v.x), "=f"(v.y) : "l"(u));
    return v;
}
__device__ __forceinline__ void fma2(unsigned long long& c, unsigned long long a,
                                     unsigned long long b) {
    asm("fma.rn.f32x2 %0, %1, %2, %3;" : "=l"(c) : "l"(a), "l"(b), "l"(c));
}
__device__ __forceinline__ unsigned long long umin64(unsigned long long a,
                                                     unsigned long long b) {
    return a < b ? a : b;
}

// ================= kernel 1: h = tanh(X @ W + b) =================
// tile 64 rows x 128 cols, kc=32, 256 threads, 4x8 per-thread via f32x2.
// A staged DUPLICATED in shared ({a,a} pairs) so inner loop has zero MOVs:
// 16 FFMA2 + 4 LDS.128 per k-step.
__global__ void __launch_bounds__(256) k_transform(const float* __restrict__ A,
                                                   const float* __restrict__ W,
                                                   const float* __restrict__ bias,
                                                   int M, int to_mem) {
    __shared__ __align__(16) float As[32][128];   // duplicated: row r at cols 2r,2r+1
    __shared__ __align__(16) float Ws[32][128];
    float* __restrict__ out = to_mem ? g_mh : g_qh;

    const int tid = threadIdx.x;
    const int rg = tid & 15;   // 16 groups x 4 rows
    const int cg = tid >> 4;   // 16 groups x 8 cols
    const int rbase = blockIdx.x * 64;
    const int cbase = blockIdx.y * 128;

    unsigned long long acc[4][4];
#pragma unroll
    for (int i = 0; i < 4; i++)
#pragma unroll
        for (int j = 0; j < 4; j++) acc[i][j] = 0ull;

    for (int ko = 0; ko < D_; ko += 32) {
        {   // A tile -> As[k][2*row{,+1}] duplicated
            int row = tid >> 2, ks = (tid & 3) * 8;
            int gr = rbase + row;
            float4 v0 = {0,0,0,0}, v1 = {0,0,0,0};
            if (gr < M) {
                const float4* p = reinterpret_cast<const float4*>(A + (size_t)gr * D_ + ko + ks);
                v0 = p[0]; v1 = p[1];
            }
            float vv[8] = {v0.x,v0.y,v0.z,v0.w,v1.x,v1.y,v1.z,v1.w};
#pragma unroll
            for (int i = 0; i < 8; i++)
                *reinterpret_cast<unsigned long long*>(&As[ks + i][2 * row]) = pk2(vv[i], vv[i]);
        }
        {   // W tile natural layout Ws[k][col]
            int kk = tid >> 3, cs = (tid & 7) * 16;
            const float4* p = reinterpret_cast<const float4*>(W + (size_t)(ko + kk) * D_ + cbase + cs);
            float4 w0 = p[0], w1 = p[1], w2 = p[2], w3 = p[3];
            float4* q = reinterpret_cast<float4*>(&Ws[kk][cs]);
            q[0] = w0; q[1] = w1; q[2] = w2; q[3] = w3;
        }
        __syncthreads();
#pragma unroll
        for (int kk = 0; kk < 32; kk++) {
            ulonglong2 a01 = *reinterpret_cast<const ulonglong2*>(&As[kk][rg * 8]);
            ulonglong2 a23 = *reinterpret_cast<const ulonglong2*>(&As[kk][rg * 8 + 4]);
            ulonglong2 b01 = *reinterpret_cast<const ulonglong2*>(&Ws[kk][cg * 8]);
            ulonglong2 b23 = *reinterpret_cast<const ulonglong2*>(&Ws[kk][cg * 8 + 4]);
            fma2(acc[0][0],a01.x,b01.x); fma2(acc[0][1],a01.x,b01.y);
            fma2(acc[0][2],a01.x,b23.x); fma2(acc[0][3],a01.x,b23.y);
            fma2(acc[1][0],a01.y,b01.x); fma2(acc[1][1],a01.y,b01.y);
            fma2(acc[1][2],a01.y,b23.x); fma2(acc[1][3],a01.y,b23.y);
            fma2(acc[2][0],a23.x,b01.x); fma2(acc[2][1],a23.x,b01.y);
            fma2(acc[2][2],a23.x,b23.x); fma2(acc[2][3],a23.x,b23.y);
            fma2(acc[3][0],a23.y,b01.x); fma2(acc[3][1],a23.y,b01.y);
            fma2(acc[3][2],a23.y,b23.x); fma2(acc[3][3],a23.y,b23.y);
        }
        __syncthreads();
    }
#pragma unroll
    for (int i = 0; i < 4; i++) {
        int r = rbase + rg * 4 + i;
        if (r < M) {
#pragma unroll
            for (int j = 0; j < 4; j++) {
                float2 v = up2(acc[i][j]);
                int c = cbase + cg * 8 + j * 2;
                out[(size_t)r * D_ + c]     = tanhf(v.x + bias[c]);
                out[(size_t)r * D_ + c + 1] = tanhf(v.y + bias[c + 1]);
            }
        }
    }
}

// ================= kernel 2: Poincare rescale + row sum-of-squares =================
// warp per row, 8 rows per block, fully vectorized
__global__ void __launch_bounds__(256) k_normalize(int which, int M) {
    float* __restrict__ h  = which ? g_mh  : g_qh;
    float* __restrict__ sq = which ? g_msq : g_qsq;
    int row = blockIdx.x * 8 + (threadIdx.x >> 5);
    if (row >= M) return;
    int lane = threadIdx.x & 31;
    float4* p = reinterpret_cast<float4*>(h + (size_t)row * D_ + lane * 8);
    float4 v0 = p[0], v1 = p[1];
    float s = v0.x*v0.x + v0.y*v0.y + v0.z*v0.z + v0.w*v0.w
            + v1.x*v1.x + v1.y*v1.y + v1.z*v1.z + v1.w*v1.w;
#pragma unroll
    for (int o = 16; o; o >>= 1) s += __shfl_xor_sync(0xffffffffu, s, o);
    float norm = sqrtf(s);
    float scale = (norm > 0.95f) ? (0.95f / norm) : 1.0f;
    v0.x *= scale; v0.y *= scale; v0.z *= scale; v0.w *= scale;
    v1.x *= scale; v1.y *= scale; v1.z *= scale; v1.w *= scale;
    p[0] = v0; p[1] = v1;
    float s2 = v0.x*v0.x + v0.y*v0.y + v0.z*v0.z + v0.w*v0.w
             + v1.x*v1.x + v1.y*v1.y + v1.z*v1.z + v1.w*v1.w;
#pragma unroll
    for (int o = 16; o; o >>= 1) s2 += __shfl_xor_sync(0xffffffffu, s2, o);
    if (lane == 0) sq[row] = s2;
}

// ================= kernel 3: distance GEMM -> arg matrix =================
// tile 64 q x 128 m, kc=32; Q staged duplicated, zero-MOV inner loop
__global__ void __launch_bounds__(256) k_dist() {
    __shared__ __align__(16) float Qs[32][128];   // duplicated pairs
    __shared__ __align__(16) float Ms[32][128];
    const int tid = threadIdx.x;
    const int qg = tid & 15;
    const int mg = tid >> 4;
    const int qbase = blockIdx.x * 64;
    const int mb = blockIdx.y * 128;

    unsigned long long acc[4][4];
#pragma unroll
    for (int i = 0; i < 4; i++)
#pragma unroll
        for (int j = 0; j < 4; j++) acc[i][j] = 0ull;

    for (int ko = 0; ko < D_; ko += 32) {
        {   // Q tile 64x32, duplicated into Qs[k][2*row{,+1}]
            int row = tid >> 2, ks = (tid & 3) * 8;
            const float4* p = reinterpret_cast<const float4*>(g_qh + (size_t)(qbase + row) * D_ + ko + ks);
            float4 v0 = p[0], v1 = p[1];
            float vv[8] = {v0.x,v0.y,v0.z,v0.w,v1.x,v1.y,v1.z,v1.w};
#pragma unroll
            for (int i = 0; i < 8; i++)
                *reinterpret_cast<unsigned long long*>(&Qs[ks + i][2 * row]) = pk2(vv[i], vv[i]);
        }
        {   // M tile 128x32 transposed
            int mrow = tid >> 1, ks = (tid & 1) * 16;
            int gm = mb + mrow;
            float4 v0={0,0,0,0}, v1={0,0,0,0}, v2={0,0,0,0}, v3={0,0,0,0};
            if (gm < N_) {
                const float4* p = reinterpret_cast<const float4*>(g_mh + (size_t)gm * D_ + ko + ks);
                v0 = p[0]; v1 = p[1]; v2 = p[2]; v3 = p[3];
            }
            Ms[ks+ 0][mrow]=v0.x; Ms[ks+ 1][mrow]=v0.y; Ms[ks+ 2][mrow]=v0.z; Ms[ks+ 3][mrow]=v0.w;
            Ms[ks+ 4][mrow]=v1.x; Ms[ks+ 5][mrow]=v1.y; Ms[ks+ 6][mrow]=v1.z; Ms[ks+ 7][mrow]=v1.w;
            Ms[ks+ 8][mrow]=v2.x; Ms[ks+ 9][mrow]=v2.y; Ms[ks+10][mrow]=v2.z; Ms[ks+11][mrow]=v2.w;
            Ms[ks+12][mrow]=v3.x; Ms[ks+13][mrow]=v3.y; Ms[ks+14][mrow]=v3.z; Ms[ks+15][mrow]=v3.w;
        }
        __syncthreads();
#pragma unroll
        for (int kk = 0; kk < 32; kk++) {
            ulonglong2 a01 = *reinterpret_cast<const ulonglong2*>(&Qs[kk][qg * 8]);
            ulonglong2 a23 = *reinterpret_cast<const ulonglong2*>(&Qs[kk][qg * 8 + 4]);
            ulonglong2 b01 = *reinterpret_cast<const ulonglong2*>(&Ms[kk][mg * 8]);
            ulonglong2 b23 = *reinterpret_cast<const ulonglong2*>(&Ms[kk][mg * 8 + 4]);
            fma2(acc[0][0],a01.x,b01.x); fma2(acc[0][1],a01.x,b01.y);
            fma2(acc[0][2],a01.x,b23.x); fma2(acc[0][3],a01.x,b23.y);
            fma2(acc[1][0],a01.y,b01.x); fma2(acc[1][1],a01.y,b01.y);
            fma2(acc[1][2],a01.y,b23.x); fma2(acc[1][3],a01.y,b23.y);
            fma2(acc[2][0],a23.x,b01.x); fma2(acc[2][1],a23.x,b01.y);
            fma2(acc[2][2],a23.x,b23.x); fma2(acc[2][3],a23.x,b23.y);
            fma2(acc[3][0],a23.y,b01.x); fma2(acc[3][1],a23.y,b01.y);
            fma2(acc[3][2],a23.y,b23.x); fma2(acc[3][3],a23.y,b23.y);
        }
        __syncthreads();
    }

    // epilogue: hyperbolic arg, store
    const int gbase = mb + mg * 8;
    float msv[8];
#pragma unroll
    for (int j = 0; j < 8; j++) {
        int gm = gbase + j;
        msv[j] = (gm < N_) ? g_msq[gm] : 0.0f;
    }
#pragma unroll
    for (int i = 0; i < 4; i++) {
        int q = qbase + qg * 4 + i;
        float myq = g_qsq[q];
        float qa = 1.0f - myq;
#pragma unroll
        for (int jj = 0; jj < 4; jj++) {
            float2 d = up2(acc[i][jj]);
#pragma unroll
            for (int h = 0; h < 2; h++) {
                int j = jj * 2 + h;
                int gm = gbase + j;
                if (gm < N_) {
                    float dot = h ? d.y : d.x;
                    float diff = fmaxf(myq + msv[j] - 2.0f * dot, 0.0f);
                    float denom = qa * (1.0f - msv[j]) + 1e-8f;
                    float arg = 1.0f + (2.0f * diff) / denom;
                    g_arg[(size_t)q * N_ + gm] = arg;
                }
            }
        }
    }
}

// ================= kernel 4: per-query top-8, softmax, gather =================
__global__ void __launch_bounds__(256) k_topk(const float* __restrict__ masks,
                                              float* __restrict__ out) {
    const int q = blockIdx.x, tid = threadIdx.x;
    const float4* __restrict__ row4 =
        reinterpret_cast<const float4*>(g_arg + (size_t)q * N_);

    unsigned long long best[K_];
#pragma unroll
    for (int s = 0; s < K_; s++) best[s] = ~0ull;

    // vectorized scan: key = (arg_bits << 32) | idx (ascending arg, then idx)
    for (int i = tid; i < N_ / 4; i += 256) {
        float4 a = row4[i];
        float av[4] = {a.x, a.y, a.z, a.w};
#pragma unroll
        for (int c = 0; c < 4; c++) {
            unsigned long long key =
                ((unsigned long long)__float_as_uint(av[c]) << 32) | (unsigned)(4 * i + c);
            if (key < best[K_ - 1]) {
                best[K_ - 1] = key;
#pragma unroll
                for (int s = K_ - 1; s > 0; s--) {
                    if (best[s] < best[s - 1]) {
                        unsigned long long t = best[s]; best[s] = best[s - 1]; best[s - 1] = t;
                    }
                }
            }
        }
    }

    __shared__ unsigned long long red[8];
    __shared__ unsigned long long wks;
    __shared__ float sarg[K_];
    __shared__ int sidx[K_];

    for (int s = 0; s < K_; s++) {
        unsigned long long lm = best[0];
#pragma unroll
        for (int o = 16; o; o >>= 1)
            lm = umin64(lm, __shfl_xor_sync(0xffffffffu, lm, o));
        if ((tid & 31) == 0) red[tid >> 5] = lm;
        __syncthreads();
        if (tid == 0) {
            unsigned long long m = red[0];
#pragma unroll
            for (int i = 1; i < 8; i++) m = umin64(m, red[i]);
            wks = m;
            sarg[s] = __uint_as_float((unsigned)(m >> 32));
            sidx[s] = (int)(unsigned)(m & 0xffffffffu);
        }
        __syncthreads();
        if (best[0] == wks) {   // keys unique: exactly one owner pops
#pragma unroll
            for (int i = 0; i < K_ - 1; i++) best[i] = best[i + 1];
            best[K_ - 1] = ~0ull;
        }
        __syncthreads();
    }

    // softmax over -dist (dists ascending -> d[0] is min)
    if (tid == 0) {
        float d[K_], w[K_], sum = 0.0f;
#pragma unroll
        for (int s = 0; s < K_; s++)
            d[s] = acoshf(fmaxf(sarg[s], 1.0f + 1e-6f));
#pragma unroll
        for (int s = 0; s < K_; s++) { w[s] = expf(d[0] - d[s]); sum += w[s]; }
#pragma unroll
        for (int s = 0; s < K_; s++)
            out[(size_t)q * K_ + s] = w[s] / sum;
    }
    __syncthreads();

    // gather som_hints: out[B*K + (q*K+s)*MA + t]
    float* __restrict__ hints = out + (size_t)B_ * K_;
    for (int s = 0; s < K_; s++) {
        const float* __restrict__ src = masks + (size_t)sidx[s] * MA_;
        float* __restrict__ dst = hints + ((size_t)q * K_ + s) * MA_;
        for (int t = tid; t < MA_; t += 256) dst[t] = src[t];
    }
}

extern "C" void kernel_launch(void* const* d_in, const int* in_sizes, int n_in,
                              void* d_out, int out_size) {
    const float* q_emb  = (const float*)d_in[0];
    const float* m_emb  = (const float*)d_in[1];
    const float* masks  = (const float*)d_in[2];
    const float* W      = (const float*)d_in[3];
    const float* b      = (const float*)d_in[4];
    float* out = (float*)d_out;

    k_transform<<<dim3(B_ / 64, D_ / 128), 256>>>(q_emb, W, b, B_, 0);
    k_transform<<<dim3((N_ + 63) / 64, D_ / 128), 256>>>(m_emb, W, b, N_, 1);
    k_normalize<<<(B_ + 7) / 8, 256>>>(0, B_);
    k_normalize<<<(N_ + 7) / 8, 256>>>(1, N_);
    k_dist<<<dim3(B_ / 64, (N_ + 127) / 128), 256>>>();
    k_topk<<<B_, 256>>>(masks, out);
}

// round 7
// speedup vs baseline: 1.5080x; 1.5080x over previous
#include <cuda_runtime.h>
#include <cfloat>
#include <math.h>

#define B_  1024
#define N_  50000
#define D_  256
#define MA_ 200
#define K_  8

// ---------- device scratch ----------
__device__ float g_qh[B_ * D_];
__device__ float g_mh[(size_t)N_ * D_];
__device__ float g_qsq[B_];
__device__ float g_msq[N_];
__device__ float g_arg[(size_t)B_ * N_];   // ~195 MB

// ---------- packed f32x2 helpers ----------
__device__ __forceinline__ unsigned long long pk2(float x, float y) {
    unsigned long long u;
    asm("mov.b64 %0, {%1,%2};" : "=l"(u) : "f"(x), "f"(y));
    return u;
}
__device__ __forceinline__ float2 up2(unsigned long long u) {
    float2 v;
    asm("mov.b64 {%0,%1}, %2;" : "=f"(v.x), "=f"(v.y) : "l"(u));
    return v;
}
__device__ __forceinline__ void fma2(unsigned long long& c, unsigned long long a,
                                     unsigned long long b) {
    asm("fma.rn.f32x2 %0, %1, %2, %3;" : "=l"(c) : "l"(a), "l"(b), "l"(c));
}
__device__ __forceinline__ unsigned long long umin64(unsigned long long a,
                                                     unsigned long long b) {
    return a < b ? a : b;
}

// Shared inner micro-kernel: 8q x 4m per thread, q broadcast, m coalesced.
// As: [32][64] k-major (row r of tile at As[kk*64 + r]), Bs: [32][128].
#define MICRO_KK(kk)                                                          \
    {                                                                         \
        float4 q0 = *reinterpret_cast<const float4*>(&As[(kk) * 64 + w8]);    \
        float4 q1 = *reinterpret_cast<const float4*>(&As[(kk) * 64 + w8 + 4]);\
        ulonglong2 b = *reinterpret_cast<const ulonglong2*>(&Bs[(kk) * 128 + lane4]); \
        unsigned long long a0 = pk2(q0.x, q0.x), a1 = pk2(q0.y, q0.y);        \
        unsigned long long a2 = pk2(q0.z, q0.z), a3 = pk2(q0.w, q0.w);        \
        unsigned long long a4 = pk2(q1.x, q1.x), a5 = pk2(q1.y, q1.y);        \
        unsigned long long a6 = pk2(q1.z, q1.z), a7 = pk2(q1.w, q1.w);        \
        fma2(acc[0][0], a0, b.x); fma2(acc[0][1], a0, b.y);                   \
        fma2(acc[1][0], a1, b.x); fma2(acc[1][1], a1, b.y);                   \
        fma2(acc[2][0], a2, b.x); fma2(acc[2][1], a2, b.y);                   \
        fma2(acc[3][0], a3, b.x); fma2(acc[3][1], a3, b.y);                   \
        fma2(acc[4][0], a4, b.x); fma2(acc[4][1], a4, b.y);                   \
        fma2(acc[5][0], a5, b.x); fma2(acc[5][1], a5, b.y);                   \
        fma2(acc[6][0], a6, b.x); fma2(acc[6][1], a6, b.y);                   \
        fma2(acc[7][0], a7, b.x); fma2(acc[7][1], a7, b.y);                   \
    }

// ================= kernel 1: h = tanh(X @ W + b) =================
// block tile 64 rows x 128 cols, warp = 8 rows x 128 cols, lane = 8x4
__global__ void __launch_bounds__(256, 2) k_transform(const float* __restrict__ A,
                                                      const float* __restrict__ W,
                                                      const float* __restrict__ bias,
                                                      int M, int to_mem) {
    __shared__ __align__(16) float As[32 * 64];
    __shared__ __align__(16) float Bs[32 * 128];
    float* __restrict__ out = to_mem ? g_mh : g_qh;

    const int tid = threadIdx.x;
    const int w8 = (tid >> 5) * 8;     // warp's q-row group * 8
    const int lane4 = (tid & 31) * 4;  // lane's col * 4
    const int rbase = blockIdx.x * 64;
    const int cbase = blockIdx.y * 128;

    unsigned long long acc[8][2];
#pragma unroll
    for (int i = 0; i < 8; i++) { acc[i][0] = 0ull; acc[i][1] = 0ull; }

    const int sr = tid & 63;           // staging: row
    const int skq = tid >> 6;          // staging: k-quarter (8 k each)
    const int wkw = tid >> 3;          // W staging: k row
    const int wcs = (tid & 7) * 16;    // W staging: col start

    for (int ko = 0; ko < D_; ko += 32) {
        {   // A tile: 64 rows x 32 k -> As[k][row]; lanes -> distinct banks
            int gr = rbase + sr;
            float4 v0 = {0,0,0,0}, v1 = {0,0,0,0};
            if (gr < M) {
                const float4* p = reinterpret_cast<const float4*>(A + (size_t)gr * D_ + ko + skq * 8);
                v0 = p[0]; v1 = p[1];
            }
            float vv[8] = {v0.x,v0.y,v0.z,v0.w,v1.x,v1.y,v1.z,v1.w};
#pragma unroll
            for (int i = 0; i < 8; i++) As[(skq * 8 + i) * 64 + sr] = vv[i];
        }
        {   // W tile: 32 k x 128 cols natural, contiguous float4
            const float4* p = reinterpret_cast<const float4*>(W + (size_t)(ko + wkw) * D_ + cbase + wcs);
            float4 w0 = p[0], w1 = p[1], w2 = p[2], w3 = p[3];
            float4* q = reinterpret_cast<float4*>(&Bs[wkw * 128 + wcs]);
            q[0] = w0; q[1] = w1; q[2] = w2; q[3] = w3;
        }
        __syncthreads();
#pragma unroll
        for (int kk = 0; kk < 32; kk++) MICRO_KK(kk)
        __syncthreads();
    }

    const int c0 = cbase + lane4;
    float4 b4 = *reinterpret_cast<const float4*>(bias + c0);
#pragma unroll
    for (int i = 0; i < 8; i++) {
        int r = rbase + w8 + i;
        if (r < M) {
            float2 v0 = up2(acc[i][0]), v1 = up2(acc[i][1]);
            float4 o;
            o.x = tanhf(v0.x + b4.x); o.y = tanhf(v0.y + b4.y);
            o.z = tanhf(v1.x + b4.z); o.w = tanhf(v1.y + b4.w);
            *reinterpret_cast<float4*>(out + (size_t)r * D_ + c0) = o;
        }
    }
}

// ================= kernel 2: Poincare rescale + row sum-of-squares =================
__global__ void __launch_bounds__(256) k_normalize(int which, int M) {
    float* __restrict__ h  = which ? g_mh  : g_qh;
    float* __restrict__ sq = which ? g_msq : g_qsq;
    int row = blockIdx.x * 8 + (threadIdx.x >> 5);
    if (row >= M) return;
    int lane = threadIdx.x & 31;
    float4* p = reinterpret_cast<float4*>(h + (size_t)row * D_ + lane * 8);
    float4 v0 = p[0], v1 = p[1];
    float s = v0.x*v0.x + v0.y*v0.y + v0.z*v0.z + v0.w*v0.w
            + v1.x*v1.x + v1.y*v1.y + v1.z*v1.z + v1.w*v1.w;
#pragma unroll
    for (int o = 16; o; o >>= 1) s += __shfl_xor_sync(0xffffffffu, s, o);
    float norm = sqrtf(s);
    float scale = (norm > 0.95f) ? (0.95f / norm) : 1.0f;
    v0.x *= scale; v0.y *= scale; v0.z *= scale; v0.w *= scale;
    v1.x *= scale; v1.y *= scale; v1.z *= scale; v1.w *= scale;
    p[0] = v0; p[1] = v1;
    float s2 = v0.x*v0.x + v0.y*v0.y + v0.z*v0.z + v0.w*v0.w
             + v1.x*v1.x + v1.y*v1.y + v1.z*v1.z + v1.w*v1.w;
#pragma unroll
    for (int o = 16; o; o >>= 1) s2 += __shfl_xor_sync(0xffffffffu, s2, o);
    if (lane == 0) sq[row] = s2;
}

// ================= kernel 3: distance GEMM -> arg matrix =================
// block 64q x 128m; warp = 8q x 128m; lane = 8q x 4m. Coalesced epilogue.
__global__ void __launch_bounds__(256, 2) k_dist() {
    __shared__ __align__(16) float As[32 * 64];    // Q tile, k-major
    __shared__ __align__(16) float Bs[32 * 128];   // M tile, k-major
    const int tid = threadIdx.x;
    const int w8 = (tid >> 5) * 8;
    const int lane4 = (tid & 31) * 4;
    const int qbase = blockIdx.x * 64;
    const int mb = blockIdx.y * 128;

    unsigned long long acc[8][2];
#pragma unroll
    for (int i = 0; i < 8; i++) { acc[i][0] = 0ull; acc[i][1] = 0ull; }

    const int sr = tid & 63;
    const int skq = tid >> 6;
    const int mrow = tid & 127;        // M staging: m row (banks 0..31 per warp)
    const int mkh = tid >> 7;          // M staging: k half (16 k each)

    for (int ko = 0; ko < D_; ko += 32) {
        {   // Q tile: 64 x 32 -> As[k][row]
            const float4* p = reinterpret_cast<const float4*>(g_qh + (size_t)(qbase + sr) * D_ + ko + skq * 8);
            float4 v0 = p[0], v1 = p[1];
            float vv[8] = {v0.x,v0.y,v0.z,v0.w,v1.x,v1.y,v1.z,v1.w};
#pragma unroll
            for (int i = 0; i < 8; i++) As[(skq * 8 + i) * 64 + sr] = vv[i];
        }
        {   // M tile: 128 x 32 -> Bs[k][mrow], conflict-free scatter
            int gm = mb + mrow;
            float4 v0={0,0,0,0}, v1={0,0,0,0}, v2={0,0,0,0}, v3={0,0,0,0};
            if (gm < N_) {
                const float4* p = reinterpret_cast<const float4*>(g_mh + (size_t)gm * D_ + ko + mkh * 16);
                v0 = p[0]; v1 = p[1]; v2 = p[2]; v3 = p[3];
            }
            float vv[16] = {v0.x,v0.y,v0.z,v0.w, v1.x,v1.y,v1.z,v1.w,
                            v2.x,v2.y,v2.z,v2.w, v3.x,v3.y,v3.z,v3.w};
#pragma unroll
            for (int i = 0; i < 16; i++) Bs[(mkh * 16 + i) * 128 + mrow] = vv[i];
        }
        __syncthreads();
#pragma unroll
        for (int kk = 0; kk < 32; kk++) MICRO_KK(kk)
        __syncthreads();
    }

    // epilogue: hyperbolic arg; warp-uniform rows -> coalesced float4 stores
    const int gm0 = mb + lane4;
    if (gm0 < N_) {
        float4 ms4 = *reinterpret_cast<const float4*>(g_msq + gm0);
        float4 ma; // 1 - msq
        ma.x = 1.0f - ms4.x; ma.y = 1.0f - ms4.y; ma.z = 1.0f - ms4.z; ma.w = 1.0f - ms4.w;
#pragma unroll
        for (int i = 0; i < 8; i++) {
            int q = qbase + w8 + i;
            float myq = g_qsq[q];
            float qa = 1.0f - myq;
            float2 d0 = up2(acc[i][0]), d1 = up2(acc[i][1]);
            float4 o;
            {
                float diff = fmaxf(myq + ms4.x - 2.0f * d0.x, 0.0f);
                o.x = 1.0f + (2.0f * diff) / (qa * ma.x + 1e-8f);
            }
            {
                float diff = fmaxf(myq + ms4.y - 2.0f * d0.y, 0.0f);
                o.y = 1.0f + (2.0f * diff) / (qa * ma.y + 1e-8f);
            }
            {
                float diff = fmaxf(myq + ms4.z - 2.0f * d1.x, 0.0f);
                o.z = 1.0f + (2.0f * diff) / (qa * ma.z + 1e-8f);
            }
            {
                float diff = fmaxf(myq + ms4.w - 2.0f * d1.y, 0.0f);
                o.w = 1.0f + (2.0f * diff) / (qa * ma.w + 1e-8f);
            }
            *reinterpret_cast<float4*>(g_arg + (size_t)q * N_ + gm0) = o;
        }
    }
}

// ================= kernel 4: per-query top-8, softmax, gather =================
__global__ void __launch_bounds__(256) k_topk(const float* __restrict__ masks,
                                              float* __restrict__ out) {
    const int q = blockIdx.x, tid = threadIdx.x;
    const float4* __restrict__ row4 =
        reinterpret_cast<const float4*>(g_arg + (size_t)q * N_);

    unsigned long long best[K_];
#pragma unroll
    for (int s = 0; s < K_; s++) best[s] = 0x7F800000FFFFFFFFull;  // (+inf, idx max)
    float bmax = __int_as_float(0x7F800000);                       // +inf

    for (int i = tid; i < N_ / 4; i += 256) {
        float4 a = row4[i];
        float av[4] = {a.x, a.y, a.z, a.w};
#pragma unroll
        for (int c = 0; c < 4; c++) {
            if (av[c] <= bmax) {   // cheap filter; <= handles idx tie-break
                unsigned long long key =
                    ((unsigned long long)__float_as_uint(av[c]) << 32) | (unsigned)(4 * i + c);
                if (key < best[K_ - 1]) {
                    best[K_ - 1] = key;
#pragma unroll
                    for (int s = K_ - 1; s > 0; s--) {
                        if (best[s] < best[s - 1]) {
                            unsigned long long t = best[s]; best[s] = best[s - 1]; best[s - 1] = t;
                        }
                    }
                    bmax = __uint_as_float((unsigned)(best[K_ - 1] >> 32));
                }
            }
        }
    }

    __shared__ unsigned long long red[8];
    __shared__ unsigned long long wks;
    __shared__ float sarg[K_];
    __shared__ int sidx[K_];

    for (int s = 0; s < K_; s++) {
        unsigned long long lm = best[0];
#pragma unroll
        for (int o = 16; o; o >>= 1)
            lm = umin64(lm, __shfl_xor_sync(0xffffffffu, lm, o));
        if ((tid & 31) == 0) red[tid >> 5] = lm;
        __syncthreads();
        if (tid == 0) {
            unsigned long long m = red[0];
#pragma unroll
            for (int i = 1; i < 8; i++) m = umin64(m, red[i]);
            wks = m;
            sarg[s] = __uint_as_float((unsigned)(m >> 32));
            sidx[s] = (int)(unsigned)(m & 0xffffffffu);
        }
        __syncthreads();
        if (best[0] == wks) {   // keys unique: exactly one owner pops
#pragma unroll
            for (int i = 0; i < K_ - 1; i++) best[i] = best[i + 1];
            best[K_ - 1] = 0x7F800000FFFFFFFFull;
        }
        __syncthreads();
    }

    if (tid == 0) {
        float d[K_], w[K_], sum = 0.0f;
#pragma unroll
        for (int s = 0; s < K_; s++)
            d[s] = acoshf(fmaxf(sarg[s], 1.0f + 1e-6f));
#pragma unroll
        for (int s = 0; s < K_; s++) { w[s] = expf(d[0] - d[s]); sum += w[s]; }
#pragma unroll
        for (int s = 0; s < K_; s++)
            out[(size_t)q * K_ + s] = w[s] / sum;
    }
    __syncthreads();

    float* __restrict__ hints = out + (size_t)B_ * K_;
    for (int s = 0; s < K_; s++) {
        const float* __restrict__ src = masks + (size_t)sidx[s] * MA_;
        float* __restrict__ dst = hints + ((size_t)q * K_ + s) * MA_;
        for (int t = tid; t < MA_; t += 256) dst[t] = src[t];
    }
}

extern "C" void kernel_launch(void* const* d_in, const int* in_sizes, int n_in,
                              void* d_out, int out_size) {
    const float* q_emb  = (const float*)d_in[0];
    const float* m_emb  = (const float*)d_in[1];
    const float* masks  = (const float*)d_in[2];
    const float* W      = (const float*)d_in[3];
    const float* b      = (const float*)d_in[4];
    float* out = (float*)d_out;

    k_transform<<<dim3(B_ / 64, 2), 256>>>(q_emb, W, b, B_, 0);
    k_transform<<<dim3((N_ + 63) / 64, 2), 256>>>(m_emb, W, b, N_, 1);
    k_normalize<<<(B_ + 7) / 8, 256>>>(0, B_);
    k_normalize<<<(N_ + 7) / 8, 256>>>(1, N_);
    k_dist<<<dim3(B_ / 64, (N_ + 127) / 128), 256>>>();
    k_topk<<<B_, 256>>>(masks, out);
}